// round 4
// baseline (speedup 1.0000x reference)
#include <cuda_runtime.h>

#define NN 100000
#define EE 1600000
#define DD 128
#define ET (EE + NN)

// ---------------- scratch (static device globals; no allocations) ----------
__device__ int   g_flag;           // nonzero => edge_index is int32
__device__ int   g_deg[NN];        // degree over row incl. self loop
__device__ int   g_cnt[NN];        // in-degree over col incl. self loop
__device__ int   g_off[NN + 1];    // CSR offsets by col
__device__ int   g_cur[NN];        // fill cursors
__device__ float g_dis[NN];        // deg^-0.5
__device__ int2  g_edges[ET];      // (src, weight-as-bits), grouped by dst
__device__ float g_P[(size_t)NN * DD];  // projected features (GEMM out, pull in)
__device__ float g_H[(size_t)NN * DD];  // hidden features (pull out, GEMM in)

// ---------------- dtype handling --------------------------------------------
// If edge_index is int64, all high 32-bit words are zero (values in [0, 1e5)).
// If it is int32, the odd words are real indices (virtually never all zero).
__global__ void k_detect(const int* __restrict__ ei32) {
    int t = blockIdx.x * blockDim.x + threadIdx.x;
    if (t == 0) g_flag = 0;   // separate kernel ordering not needed: see OR below
    __syncthreads();
    // scan words 1,3,5,... up to 8191 (within the smallest possible buffer)
    int w = 0;
    for (int i = t; i < 4096; i += blockDim.x * gridDim.x)
        w |= ei32[2 * i + 1];
    if (w != 0) atomicOr(&g_flag, 1);
}

__device__ __forceinline__ int ld_idx(const void* ei, long long pos, bool is32) {
    return is32 ? ((const int*)ei)[pos] : (int)((const long long*)ei)[pos];
}

// ---------------- preprocessing --------------------------------------------
__global__ void k_init() {
    int i = blockIdx.x * blockDim.x + threadIdx.x;
    if (i < NN) { g_deg[i] = 1; g_cnt[i] = 1; g_cur[i] = 0; }
}

__global__ void k_count(const void* __restrict__ ei) {
    int e = blockIdx.x * blockDim.x + threadIdx.x;
    bool is32 = (g_flag != 0);
    if (e < EE) {
        int r = ld_idx(ei, e, is32);
        int c = ld_idx(ei, (long long)EE + e, is32);
        if ((unsigned)r < NN && (unsigned)c < NN) {
            atomicAdd(&g_deg[r], 1);   // row (source)
            atomicAdd(&g_cnt[c], 1);   // col (target)
        }
    }
}

__global__ void k_dis() {
    int i = blockIdx.x * blockDim.x + threadIdx.x;
    if (i < NN) g_dis[i] = rsqrtf((float)g_deg[i]);
}

// exclusive scan of g_cnt -> g_off, single block of 1024 threads
__global__ __launch_bounds__(1024) void k_scan() {
    const int T = 1024;
    const int C = (NN + T - 1) / T;   // 98
    int t = threadIdx.x;
    int base = t * C;
    int s = 0;
    for (int j = 0; j < C; j++) { int idx = base + j; if (idx < NN) s += g_cnt[idx]; }
    __shared__ int ps[T];
    ps[t] = s;
    __syncthreads();
    for (int d = 1; d < T; d <<= 1) {
        int v = (t >= d) ? ps[t - d] : 0;
        __syncthreads();
        ps[t] += v;
        __syncthreads();
    }
    int run = ps[t] - s;  // exclusive prefix
    for (int j = 0; j < C; j++) {
        int idx = base + j;
        if (idx < NN) { g_off[idx] = run; run += g_cnt[idx]; }
    }
    if (t == T - 1) g_off[NN] = run;  // base beyond NN => run == grand total
}

// scatter edges (and self loops) into CSR-by-col with fused weights
__global__ void k_fill(const void* __restrict__ ei) {
    int e = blockIdx.x * blockDim.x + threadIdx.x;
    bool is32 = (g_flag != 0);
    if (e < EE) {
        int r = ld_idx(ei, e, is32);
        int c = ld_idx(ei, (long long)EE + e, is32);
        if ((unsigned)r < NN && (unsigned)c < NN) {
            int pos = g_off[c] + atomicAdd(&g_cur[c], 1);
            g_edges[pos] = make_int2(r, __float_as_int(g_dis[r] * g_dis[c]));
        }
    } else if (e < ET) {
        int i = e - EE;
        int pos = g_off[i] + atomicAdd(&g_cur[i], 1);
        float d = g_dis[i];
        g_edges[pos] = make_int2(i, __float_as_int(d * d));
    }
}

// ---------------- GEMM: g_P[N,128] = A[N,128] @ W^T + b --------------------
// BM=64 rows/block, BN=128 (all cols), BK=32, 256 threads, 4x8 register tile.
template <bool USE_H>
__global__ __launch_bounds__(256) void k_gemm(const float* __restrict__ Ax,
                                              const float* __restrict__ Wm,
                                              const float* __restrict__ bias) {
    __shared__ __align__(16) float sA[64][36];
    __shared__ __align__(16) float sW[32][132];

    const float* __restrict__ A = USE_H ? (const float*)g_H : Ax;

    int t = threadIdx.x;
    int trow = t >> 4;   // 0..15 -> rows trow*4..+3
    int tcol = t & 15;   // 0..15 -> cols tcol*8..+7
    int rowBase = blockIdx.x * 64;

    float acc[4][8];
#pragma unroll
    for (int r = 0; r < 4; r++)
#pragma unroll
        for (int c = 0; c < 8; c++) acc[r][c] = 0.f;

    for (int kt = 0; kt < 4; kt++) {
#pragma unroll
        for (int i = 0; i < 2; i++) {
            int idx = t + i * 256;
            int r = idx >> 3, c4 = idx & 7;
            int gr = rowBase + r;
            float4 v = make_float4(0.f, 0.f, 0.f, 0.f);
            if (gr < NN)
                v = *(const float4*)(A + (size_t)gr * DD + kt * 32 + c4 * 4);
            *(float4*)&sA[r][c4 * 4] = v;
        }
#pragma unroll
        for (int i = 0; i < 4; i++) {
            int idx = t + i * 256;
            int d = idx >> 3, k4 = idx & 7;
            float4 v = *(const float4*)(Wm + d * DD + kt * 32 + k4 * 4);
            sW[k4 * 4 + 0][d] = v.x;
            sW[k4 * 4 + 1][d] = v.y;
            sW[k4 * 4 + 2][d] = v.z;
            sW[k4 * 4 + 3][d] = v.w;
        }
        __syncthreads();

#pragma unroll
        for (int k4 = 0; k4 < 8; k4++) {
            float4 af[4];
#pragma unroll
            for (int r = 0; r < 4; r++)
                af[r] = *(float4*)&sA[trow * 4 + r][k4 * 4];
            const float* ap = (const float*)af;
#pragma unroll
            for (int kk = 0; kk < 4; kk++) {
                float4 b0 = *(float4*)&sW[k4 * 4 + kk][tcol * 8];
                float4 b1 = *(float4*)&sW[k4 * 4 + kk][tcol * 8 + 4];
                float bw[8] = {b0.x, b0.y, b0.z, b0.w, b1.x, b1.y, b1.z, b1.w};
#pragma unroll
                for (int r = 0; r < 4; r++) {
                    float a = ap[r * 4 + kk];
#pragma unroll
                    for (int c = 0; c < 8; c++) acc[r][c] = fmaf(a, bw[c], acc[r][c]);
                }
            }
        }
        __syncthreads();
    }

    float4 bv0 = *(const float4*)(bias + tcol * 8);
    float4 bv1 = *(const float4*)(bias + tcol * 8 + 4);
#pragma unroll
    for (int r = 0; r < 4; r++) {
        int grow = rowBase + trow * 4 + r;
        if (grow < NN) {
            float4 o0 = make_float4(acc[r][0] + bv0.x, acc[r][1] + bv0.y,
                                    acc[r][2] + bv0.z, acc[r][3] + bv0.w);
            float4 o1 = make_float4(acc[r][4] + bv1.x, acc[r][5] + bv1.y,
                                    acc[r][6] + bv1.z, acc[r][7] + bv1.w);
            float* Crow = g_P + (size_t)grow * DD + tcol * 8;
            *(float4*)Crow = o0;
            *(float4*)(Crow + 4) = o1;
        }
    }
}

// ---------------- pull aggregation + ReLU ----------------------------------
// one warp per node; lane owns cols lane*4..+3 (float4). Reads g_P.
template <bool TO_H>
__global__ __launch_bounds__(256) void k_pull(float* __restrict__ Ox) {
    int gw = (blockIdx.x * blockDim.x + threadIdx.x) >> 5;
    int lane = threadIdx.x & 31;
    if (gw >= NN) return;
    int s = g_off[gw];
    int e = g_off[gw + 1];
    const float4* __restrict__ Pb = (const float4*)g_P;
    float4 acc = make_float4(0.f, 0.f, 0.f, 0.f);
    int j = s;
    for (; j + 2 <= e; j += 2) {
        int2 e0 = g_edges[j];
        int2 e1 = g_edges[j + 1];
        float4 v0 = Pb[(size_t)e0.x * 32 + lane];
        float4 v1 = Pb[(size_t)e1.x * 32 + lane];
        float w0 = __int_as_float(e0.y);
        float w1 = __int_as_float(e1.y);
        acc.x += w0 * v0.x + w1 * v1.x;
        acc.y += w0 * v0.y + w1 * v1.y;
        acc.z += w0 * v0.z + w1 * v1.z;
        acc.w += w0 * v0.w + w1 * v1.w;
    }
    if (j < e) {
        int2 e0 = g_edges[j];
        float4 v0 = Pb[(size_t)e0.x * 32 + lane];
        float w0 = __int_as_float(e0.y);
        acc.x += w0 * v0.x;
        acc.y += w0 * v0.y;
        acc.z += w0 * v0.z;
        acc.w += w0 * v0.w;
    }
    float4 r = make_float4(fmaxf(acc.x, 0.f), fmaxf(acc.y, 0.f),
                           fmaxf(acc.z, 0.f), fmaxf(acc.w, 0.f));
    float4* Ob = TO_H ? (float4*)g_H : (float4*)Ox;
    Ob[(size_t)gw * 32 + lane] = r;
}

// ---------------- launch ----------------------------------------------------
extern "C" void kernel_launch(void* const* d_in, const int* in_sizes, int n_in,
                              void* d_out, int out_size) {
    const float* x  = (const float*)d_in[0];
    const void*  ei = d_in[1];                 // int32 or int64, detected on device
    const float* W1 = (const float*)d_in[2];
    const float* b1 = (const float*)d_in[3];
    const float* W2 = (const float*)d_in[4];
    const float* b2 = (const float*)d_in[5];
    const float* W3 = (const float*)d_in[6];
    const float* b3 = (const float*)d_in[7];
    float* out = (float*)d_out;

    const int TB = 256;
    // preprocess
    k_detect<<<1, 256>>>((const int*)ei);
    k_init  <<<(NN + TB - 1) / TB, TB>>>();
    k_count <<<(EE + TB - 1) / TB, TB>>>(ei);
    k_dis   <<<(NN + TB - 1) / TB, TB>>>();
    k_scan  <<<1, 1024>>>();
    k_fill  <<<(ET + TB - 1) / TB, TB>>>(ei);

    const int GB = (NN + 63) / 64;            // gemm blocks
    const int PB = (NN * 32 + TB - 1) / TB;   // pull blocks (warp per node)

    // layer 1: x -> P -> H
    k_gemm<false><<<GB, 256>>>(x, W1, b1);
    k_pull<true><<<PB, 256>>>(nullptr);
    // layer 2: H -> P -> H
    k_gemm<true><<<GB, 256>>>(nullptr, W2, b2);
    k_pull<true><<<PB, 256>>>(nullptr);
    // layer 3: H -> P -> out
    k_gemm<true><<<GB, 256>>>(nullptr, W3, b3);
    k_pull<false><<<PB, 256>>>(out);
}